// round 4
// baseline (speedup 1.0000x reference)
#include <cuda_runtime.h>
#include <cuda_bf16.h>

#define NCTA 128
#define NT 320
#define TT 1024
#define BB 128
#define HH 256

__device__ float g_h[BB * HH];
__device__ float g_u[BB * HH];
__device__ unsigned g_flags[4][32][8];

typedef unsigned long long ull;

__device__ __forceinline__ float4 ldcg4(const float4* p) {
    float4 v;
    asm volatile("ld.global.cg.v4.f32 {%0,%1,%2,%3}, [%4];"
                 : "=f"(v.x), "=f"(v.y), "=f"(v.z), "=f"(v.w) : "l"(p));
    return v;
}
__device__ __forceinline__ float ldcg1(const float* p) {
    float v;
    asm volatile("ld.global.cg.f32 %0, [%1];" : "=f"(v) : "l"(p));
    return v;
}
__device__ __forceinline__ float fast_tanh(float x) {
    float ax = fabsf(x);
    float e = __expf(2.0f * ax);
    float r = 1.0f - 2.0f / (e + 1.0f);
    return copysignf(r, x);
}
__device__ __forceinline__ float fast_sigmoid(float x) {
    return 1.0f / (1.0f + __expf(-x));
}

// ---- f32x2 packed helpers ----
__device__ __forceinline__ void lds_b64(ull& v, unsigned a) {
    asm volatile("ld.shared.b64 %0, [%1];" : "=l"(v) : "r"(a));
}
__device__ __forceinline__ void lds_v2b64(ull& x, ull& y, unsigned a) {
    asm volatile("ld.shared.v2.b64 {%0,%1}, [%2];" : "=l"(x), "=l"(y) : "r"(a));
}
__device__ __forceinline__ void ffma2(ull& acc, ull a, ull b) {
    asm volatile("fma.rn.f32x2 %0, %1, %2, %0;" : "+l"(acc) : "l"(a), "l"(b));
}
__device__ __forceinline__ float pairsum(ull v) {
    float lo = __uint_as_float((unsigned)v);
    float hi = __uint_as_float((unsigned)(v >> 32));
    return lo + hi;
}

// Row-group barrier: 32 CTAs (same mi), flag store + 32-lane poll.
__device__ __forceinline__ void group_bar(unsigned* fl, int nj, unsigned base, unsigned ep) {
    __syncthreads();
    if (threadIdx.x < 32) {
        if (threadIdx.x == 0) {
            asm volatile("fence.acq_rel.gpu;" ::: "memory");
            asm volatile("st.relaxed.gpu.global.u32 [%0], %1;"
                         :: "l"(fl + nj * 8), "r"(base + ep) : "memory");
        }
        unsigned v;
        unsigned* p = fl + threadIdx.x * 8;
        do {
            asm volatile("ld.relaxed.gpu.global.u32 %0, [%1];"
                         : "=r"(v) : "l"(p) : "memory");
        } while (__any_sync(0xffffffffu, (v - base) < ep));
        asm volatile("fence.acq_rel.gpu;" ::: "memory");
    }
    __syncthreads();
}

// SMEM layout (floats).  W1/W2 hold k-paired float2 elements.
#define OFF_W1S 0                        // [128 pairs][40] float2
#define OFF_W2S (OFF_W1S + 256 * 40)     // [128 pairs][16] float2
#define OFF_H4S (OFF_W2S + 256 * 16)     // [64][32][4]
#define OFF_U4S (OFF_H4S + 8192)         // [64][32][4]
#define OFF_S1  (OFF_U4S + 8192)         // [40][33]
#define OFF_S2  (OFF_S1 + 40 * 33)       // [32][33]
#define OFF_AMP (OFF_S2 + 32 * 33)       // [32]
#define OFF_COS (OFF_AMP + 32)
#define OFF_SIN (OFF_COS + 32)
#define OFF_W0  (OFF_SIN + 32)           // [3][8]
#define OFF_B1  (OFF_W0 + 24)            // [3][8]
#define OFF_BZ  (OFF_B1 + 24)            // [8]
#define OFF_BH  (OFF_BZ + 8)             // [8]
#define OFF_WOF (OFF_BH + 8)             // [256][2]
#define OFF_BO  (OFF_WOF + 512)          // [2]
#define SMEM_FLOATS (OFF_BO + 2)
#define SMEM_BYTES (SMEM_FLOATS * 4)

__global__ void __launch_bounds__(NT, 1) pgjanet_kernel(
    const float* __restrict__ x,   const float* __restrict__ h0,
    const float* __restrict__ Wa,  const float* __restrict__ ba,
    const float* __restrict__ Wp1, const float* __restrict__ bp1,
    const float* __restrict__ Wp2, const float* __restrict__ bp2,
    const float* __restrict__ Wz,  const float* __restrict__ bz,
    const float* __restrict__ Wh,  const float* __restrict__ bh,
    const float* __restrict__ Wo,  const float* __restrict__ bo,
    float* __restrict__ out)
{
    extern __shared__ float sm[];
    float2* W1p = (float2*)(sm + OFF_W1S);
    float2* W2p = (float2*)(sm + OFF_W2S);
    float* h4s = sm + OFF_H4S;
    float* u4s = sm + OFF_U4S;
    float* S1  = sm + OFF_S1;
    float* S2  = sm + OFF_S2;
    float* s_amp = sm + OFF_AMP;
    float* s_cos = sm + OFF_COS;
    float* s_sin = sm + OFF_SIN;
    float* s_w0  = sm + OFF_W0;
    float* s_b1  = sm + OFF_B1;
    float* s_bz  = sm + OFF_BZ;
    float* s_bh  = sm + OFF_BH;
    float* s_Wo  = sm + OFF_WOF;
    float* s_bo  = sm + OFF_BO;

    const unsigned w1a = (unsigned)__cvta_generic_to_shared(W1p);
    const unsigned w2a = (unsigned)__cvta_generic_to_shared(W2p);
    const unsigned h4a = (unsigned)__cvta_generic_to_shared(h4s);
    const unsigned u4a = (unsigned)__cvta_generic_to_shared(u4s);

    const int tid  = threadIdx.x;
    const int lane = tid & 31;
    const int wid  = tid >> 5;
    const int nj = blockIdx.x & 31;
    const int mi = blockIdx.x >> 5;
    const int j0 = nj * 8;
    const int r0 = mi * 32;

    unsigned* fl = &g_flags[mi][0][0];

    unsigned base = 0;
    if (tid < 32)
        asm volatile("ld.relaxed.gpu.global.u32 %0, [%1];"
                     : "=r"(base) : "l"(fl + nj * 8) : "memory");

    // ---- preload k-paired weights into SMEM ----
    for (int idx = tid; idx < 128 * 40; idx += NT) {
        int m = idx / 40, nn = idx % 40;
        int mat = nn >> 3, j = j0 + (nn & 7);
        float v0, v1;
        if      (mat == 0) { v0 = Wa [(1 + 2*m) * HH + j];  v1 = Wa [(2 + 2*m) * HH + j]; }
        else if (mat == 1) { v0 = Wp1[(1 + 2*m) * HH + j];  v1 = Wp1[(2 + 2*m) * HH + j]; }
        else if (mat == 2) { v0 = Wp2[(1 + 2*m) * HH + j];  v1 = Wp2[(2 + 2*m) * HH + j]; }
        else if (mat == 3) { v0 = Wz [(HH + 2*m) * HH + j]; v1 = Wz [(HH + 2*m + 1) * HH + j]; }
        else               { v0 = Wh [(HH + 2*m) * HH + j]; v1 = Wh [(HH + 2*m + 1) * HH + j]; }
        W1p[m * 40 + nn] = make_float2(v0, v1);
    }
    for (int idx = tid; idx < 128 * 16; idx += NT) {
        int m = idx / 16, nn = idx % 16;
        int j = j0 + (nn & 7);
        float v0, v1;
        if (nn < 8) { v0 = Wz[(2*m) * HH + j]; v1 = Wz[(2*m + 1) * HH + j]; }
        else        { v0 = Wh[(2*m) * HH + j]; v1 = Wh[(2*m + 1) * HH + j]; }
        W2p[m * 16 + nn] = make_float2(v0, v1);
    }
    for (int idx = tid; idx < 512; idx += NT) s_Wo[idx] = Wo[idx];
    if (tid < 8) {
        int j = j0 + tid;
        s_w0[tid]      = Wa [j];  s_w0[8 + tid]  = Wp1[j];  s_w0[16 + tid] = Wp2[j];
        s_b1[tid]      = ba [j];  s_b1[8 + tid]  = bp1[j];  s_b1[16 + tid] = bp2[j];
        s_bz[tid] = bz[j];        s_bh[tid] = bh[j];
    }
    if (tid == 0) { s_bo[0] = bo[0]; s_bo[1] = bo[1]; }

    unsigned ep = 0;

    for (int t = 0; t < TT; ++t) {
        // ---- stage 1: load h tile into SMEM ([kc][row][4]) ----
        const float* hsrc = (t == 0) ? h0 : g_h;
        for (int idx = tid; idx < 32 * 64; idx += NT) {
            int r = idx >> 6, kc = idx & 63;
            float4 v = ldcg4((const float4*)(hsrc + (r0 + r) * HH) + kc);
            *(float4*)&h4s[(kc * 32 + r) * 4] = v;
        }
        if (tid < 32) {
            const float* xp = x + (((r0 + tid) * TT) + t) * 2;
            float amp = __ldg(xp), ph = __ldg(xp + 1);
            s_amp[tid] = amp;
            float sv, cv; sincosf(ph, &sv, &cv);
            s_sin[tid] = sv; s_cos[tid] = cv;
        }
        __syncthreads();

        // ---- GEMM1 (f32x2): h(32x256) @ W1(256x40); lane=row, 4 cols/warp ----
        {
            ull a0 = 0, a1 = 0, a2 = 0, a3 = 0;
            unsigned hb = h4a + lane * 16;
            unsigned wb = w1a + wid * 32;
            #pragma unroll 8
            for (int m = 0; m < 128; ++m) {
                ull h2;
                lds_b64(h2, hb + (m >> 1) * 512 + (m & 1) * 8);
                ull w0, w1, w2, w3;
                lds_v2b64(w0, w1, wb + m * 320);
                lds_v2b64(w2, w3, wb + m * 320 + 16);
                ffma2(a0, h2, w0); ffma2(a1, h2, w1);
                ffma2(a2, h2, w2); ffma2(a3, h2, w3);
            }
            S1[(wid * 4 + 0) * 33 + lane] = pairsum(a0);
            S1[(wid * 4 + 1) * 33 + lane] = pairsum(a1);
            S1[(wid * 4 + 2) * 33 + lane] = pairsum(a2);
            S1[(wid * 4 + 3) * 33 + lane] = pairsum(a3);
        }
        __syncthreads();

        // ---- epilogue 1: a, p1, p2 -> u ----
        if (tid < 256) {
            int jj = tid & 7, r = tid >> 3;
            float a  = fast_tanh(S1[(0  + jj) * 33 + r] + s_amp[r] * s_w0[jj]      + s_b1[jj]);
            float p1 = fast_tanh(S1[(8  + jj) * 33 + r] + s_cos[r] * s_w0[8 + jj]  + s_b1[8 + jj]);
            float p2 = fast_tanh(S1[(16 + jj) * 33 + r] + s_sin[r] * s_w0[16 + jj] + s_b1[16 + jj]);
            g_u[(r0 + r) * HH + j0 + jj] =
                a * p1 * p2 * (1.f - a) * (1.f - p1) * (1.f - p2);
        }
        group_bar(fl, nj, base, ++ep);

        // ---- stage 2: load u tile ----
        for (int idx = tid; idx < 32 * 64; idx += NT) {
            int r = idx >> 6, kc = idx & 63;
            float4 v = ldcg4((const float4*)(g_u + (r0 + r) * HH) + kc);
            *(float4*)&u4s[(kc * 32 + r) * 4] = v;
        }
        __syncthreads();

        // ---- GEMM2 (f32x2, warps 0-7): u(32x256) @ W2(256x16), k halves ----
        if (wid < 8) {
            int kh = wid >> 2, ng = wid & 3;
            ull a0 = 0, a1 = 0, a2 = 0, a3 = 0;
            unsigned ub = u4a + lane * 16;
            unsigned wb = w2a + ng * 32;
            #pragma unroll 8
            for (int m = kh * 64; m < kh * 64 + 64; ++m) {
                ull u2;
                lds_b64(u2, ub + (m >> 1) * 512 + (m & 1) * 8);
                ull w0, w1, w2, w3;
                lds_v2b64(w0, w1, wb + m * 128);
                lds_v2b64(w2, w3, wb + m * 128 + 16);
                ffma2(a0, u2, w0); ffma2(a1, u2, w1);
                ffma2(a2, u2, w2); ffma2(a3, u2, w3);
            }
            S2[(kh * 16 + ng * 4 + 0) * 33 + lane] = pairsum(a0);
            S2[(kh * 16 + ng * 4 + 1) * 33 + lane] = pairsum(a1);
            S2[(kh * 16 + ng * 4 + 2) * 33 + lane] = pairsum(a2);
            S2[(kh * 16 + ng * 4 + 3) * 33 + lane] = pairsum(a3);
        } else if (nj == 0 && t >= 1) {
            // idle warps 8,9: output projection for step t-1 from h4s
            #pragma unroll
            for (int it = 0; it < 4; ++it) {
                int item = it * 64 + (wid - 8) * 32 + lane;
                int r = item >> 3, kk = item & 7;
                float o0 = 0.f, o1 = 0.f;
                for (int k = kk * 32; k < kk * 32 + 32; ++k) {
                    float v = h4s[(k >> 2) * 128 + r * 4 + (k & 3)];
                    o0 += v * s_Wo[k * 2];
                    o1 += v * s_Wo[k * 2 + 1];
                }
                o0 += __shfl_xor_sync(0xffffffffu, o0, 1);
                o0 += __shfl_xor_sync(0xffffffffu, o0, 2);
                o0 += __shfl_xor_sync(0xffffffffu, o0, 4);
                o1 += __shfl_xor_sync(0xffffffffu, o1, 1);
                o1 += __shfl_xor_sync(0xffffffffu, o1, 2);
                o1 += __shfl_xor_sync(0xffffffffu, o1, 4);
                if (kk == 0) {
                    float* op = out + (((r0 + r) * TT) + (t - 1)) * 2;
                    op[0] = o0 + s_bo[0];
                    op[1] = o1 + s_bo[1];
                }
            }
        }
        __syncthreads();

        // ---- epilogue 2: z, h_cand, h_new ----
        if (tid < 256) {
            int jj = tid & 7, r = tid >> 3;
            int j = j0 + jj;
            float zp = S2[(jj)      * 33 + r] + S2[(16 + jj) * 33 + r]
                     + S1[(24 + jj) * 33 + r] + s_bz[jj];
            float hp = S2[(8 + jj)  * 33 + r] + S2[(24 + jj) * 33 + r]
                     + S1[(32 + jj) * 33 + r] + s_bh[jj];
            float z  = fast_sigmoid(zp);
            float hc = fast_tanh(hp);
            float hold = h4s[(j >> 2) * 128 + r * 4 + (j & 3)];
            float hn = z * hold + (1.f - z) * hc;
            g_h[(r0 + r) * HH + j] = hn;
            if (t == TT - 1)
                out[BB * TT * 2 + (r0 + r) * HH + j] = hn;
        }
        group_bar(fl, nj, base, ++ep);
    }

    // ---- final output row t=1023 from g_h ----
    if (nj == 0 && tid < 256) {
        int r = tid >> 3, kk = tid & 7;
        float o0 = 0.f, o1 = 0.f;
        for (int k = kk * 32; k < kk * 32 + 32; ++k) {
            float v = ldcg1(&g_h[(r0 + r) * HH + k]);
            o0 += v * s_Wo[k * 2];
            o1 += v * s_Wo[k * 2 + 1];
        }
        o0 += __shfl_xor_sync(0xffffffffu, o0, 1);
        o0 += __shfl_xor_sync(0xffffffffu, o0, 2);
        o0 += __shfl_xor_sync(0xffffffffu, o0, 4);
        o1 += __shfl_xor_sync(0xffffffffu, o1, 1);
        o1 += __shfl_xor_sync(0xffffffffu, o1, 2);
        o1 += __shfl_xor_sync(0xffffffffu, o1, 4);
        if (kk == 0) {
            float* op = out + (((r0 + r) * TT) + (TT - 1)) * 2;
            op[0] = o0 + s_bo[0];
            op[1] = o1 + s_bo[1];
        }
    }
}

extern "C" void kernel_launch(void* const* d_in, const int* in_sizes, int n_in,
                              void* d_out, int out_size) {
    const float* x   = (const float*)d_in[0];
    const float* h0  = (const float*)d_in[1];
    const float* Wa  = (const float*)d_in[2];
    const float* ba  = (const float*)d_in[3];
    const float* Wp1 = (const float*)d_in[4];
    const float* bp1 = (const float*)d_in[5];
    const float* Wp2 = (const float*)d_in[6];
    const float* bp2 = (const float*)d_in[7];
    const float* Wz  = (const float*)d_in[8];
    const float* bz  = (const float*)d_in[9];
    const float* Wh  = (const float*)d_in[10];
    const float* bh  = (const float*)d_in[11];
    const float* Wo  = (const float*)d_in[12];
    const float* bo  = (const float*)d_in[13];
    float* out = (float*)d_out;

    cudaFuncSetAttribute(pgjanet_kernel,
                         cudaFuncAttributeMaxDynamicSharedMemorySize, SMEM_BYTES);
    pgjanet_kernel<<<NCTA, NT, SMEM_BYTES>>>(
        x, h0, Wa, ba, Wp1, bp1, Wp2, bp2, Wz, bz, Wh, bh, Wo, bo, out);
}

// round 6
// speedup vs baseline: 1.1579x; 1.1579x over previous
#include <cuda_runtime.h>
#include <cuda_bf16.h>

#define NCTA 128
#define NT 640
#define TT 1024
#define BB 128
#define HH 256

__device__ float g_h[BB * HH];
__device__ float g_u[BB * HH];
__device__ unsigned g_flags[4][32][8];

__device__ __forceinline__ float4 ldcg4(const float4* p) {
    float4 v;
    asm volatile("ld.global.cg.v4.f32 {%0,%1,%2,%3}, [%4];"
                 : "=f"(v.x), "=f"(v.y), "=f"(v.z), "=f"(v.w) : "l"(p));
    return v;
}
__device__ __forceinline__ float ldcg1(const float* p) {
    float v;
    asm volatile("ld.global.cg.f32 %0, [%1];" : "=f"(v) : "l"(p));
    return v;
}
__device__ __forceinline__ float fast_tanh(float x) {
    float ax = fabsf(x);
    float e = __expf(2.0f * ax);
    float r = 1.0f - 2.0f / (e + 1.0f);
    return copysignf(r, x);
}
__device__ __forceinline__ float fast_sigmoid(float x) {
    return 1.0f / (1.0f + __expf(-x));
}

// Row-group barrier: 32 CTAs (same mi), flag store + 32-lane poll in warp 0.
__device__ __forceinline__ void group_bar(unsigned* fl, int nj, unsigned base, unsigned ep) {
    __syncthreads();
    if (threadIdx.x < 32) {
        if (threadIdx.x == 0) {
            asm volatile("fence.acq_rel.gpu;" ::: "memory");
            asm volatile("st.relaxed.gpu.global.u32 [%0], %1;"
                         :: "l"(fl + nj * 8), "r"(base + ep) : "memory");
        }
        unsigned v;
        unsigned* p = fl + threadIdx.x * 8;
        do {
            asm volatile("ld.relaxed.gpu.global.u32 %0, [%1];"
                         : "=r"(v) : "l"(p) : "memory");
        } while (__any_sync(0xffffffffu, (v - base) < ep));
        asm volatile("fence.acq_rel.gpu;" ::: "memory");
    }
    __syncthreads();
}

// SMEM layout (floats)
#define OFF_W1S 0                         // [256][40]
#define OFF_W2S (OFF_W1S + 256 * 40)      // [256][16]
#define OFF_H4S (OFF_W2S + 256 * 16)      // [64][32][4]
#define OFF_U4S (OFF_H4S + 8192)          // [64][32][4]
#define OFF_S1  (OFF_U4S + 8192)          // [2][40][33]  k-half partials
#define OFF_S2  (OFF_S1 + 2 * 40 * 33)    // [4][16][33]  k-quarter partials
#define OFF_AMP (OFF_S2 + 4 * 16 * 33)    // [32]
#define OFF_COS (OFF_AMP + 32)
#define OFF_SIN (OFF_COS + 32)
#define OFF_W0  (OFF_SIN + 32)            // [3][8]
#define OFF_B1  (OFF_W0 + 24)             // [3][8]
#define OFF_BZ  (OFF_B1 + 24)             // [8]
#define OFF_BH  (OFF_BZ + 8)              // [8]
#define OFF_WOF (OFF_BH + 8)              // [256][2]
#define OFF_BO  (OFF_WOF + 512)           // [2]
#define SMEM_FLOATS (OFF_BO + 2)
#define SMEM_BYTES (SMEM_FLOATS * 4)

__global__ void __launch_bounds__(NT, 1) pgjanet_kernel(
    const float* __restrict__ x,   const float* __restrict__ h0,
    const float* __restrict__ Wa,  const float* __restrict__ ba,
    const float* __restrict__ Wp1, const float* __restrict__ bp1,
    const float* __restrict__ Wp2, const float* __restrict__ bp2,
    const float* __restrict__ Wz,  const float* __restrict__ bz,
    const float* __restrict__ Wh,  const float* __restrict__ bh,
    const float* __restrict__ Wo,  const float* __restrict__ bo,
    float* __restrict__ out)
{
    extern __shared__ float sm[];
    float* W1s = sm + OFF_W1S;
    float* W2s = sm + OFF_W2S;
    float* h4s = sm + OFF_H4S;
    float* u4s = sm + OFF_U4S;
    float* S1  = sm + OFF_S1;
    float* S2  = sm + OFF_S2;
    float* s_amp = sm + OFF_AMP;
    float* s_cos = sm + OFF_COS;
    float* s_sin = sm + OFF_SIN;
    float* s_w0  = sm + OFF_W0;
    float* s_b1  = sm + OFF_B1;
    float* s_bz  = sm + OFF_BZ;
    float* s_bh  = sm + OFF_BH;
    float* s_Wo  = sm + OFF_WOF;
    float* s_bo  = sm + OFF_BO;

    const int tid  = threadIdx.x;
    const int lane = tid & 31;
    const int wid  = tid >> 5;
    const int nj = blockIdx.x & 31;   // column slice (8 cols)
    const int mi = blockIdx.x >> 5;   // row group (32 rows)
    const int j0 = nj * 8;
    const int r0 = mi * 32;

    unsigned* fl = &g_flags[mi][0][0];

    unsigned base = 0;
    if (tid < 32)
        asm volatile("ld.relaxed.gpu.global.u32 %0, [%1];"
                     : "=r"(base) : "l"(fl + nj * 8) : "memory");

    // ---- preload loop-invariant weights into SMEM ----
    for (int idx = tid; idx < 256 * 40; idx += NT) {
        int k = idx / 40, nn = idx % 40;
        int mat = nn >> 3, j = j0 + (nn & 7);
        float v;
        if      (mat == 0) v = Wa [(1 + k) * HH + j];
        else if (mat == 1) v = Wp1[(1 + k) * HH + j];
        else if (mat == 2) v = Wp2[(1 + k) * HH + j];
        else if (mat == 3) v = Wz [(HH + k) * HH + j];
        else               v = Wh [(HH + k) * HH + j];
        W1s[k * 40 + nn] = v;
    }
    for (int idx = tid; idx < 256 * 16; idx += NT) {
        int k = idx / 16, nn = idx % 16;
        int j = j0 + (nn & 7);
        W2s[k * 16 + nn] = (nn < 8) ? Wz[k * HH + j] : Wh[k * HH + j];
    }
    for (int idx = tid; idx < 512; idx += NT) s_Wo[idx] = Wo[idx];
    if (tid < 8) {
        int j = j0 + tid;
        s_w0[tid]      = Wa [j];  s_w0[8 + tid]  = Wp1[j];  s_w0[16 + tid] = Wp2[j];
        s_b1[tid]      = ba [j];  s_b1[8 + tid]  = bp1[j];  s_b1[16 + tid] = bp2[j];
        s_bz[tid] = bz[j];        s_bh[tid] = bh[j];
    }
    if (tid == 0) { s_bo[0] = bo[0]; s_bo[1] = bo[1]; }

    unsigned ep = 0;

    for (int t = 0; t < TT; ++t) {
        // ---- stage 1: load h tile into SMEM ([kc][row][4]) ----
        const float* hsrc = (t == 0) ? h0 : g_h;
        for (int idx = tid; idx < 32 * 64; idx += NT) {
            int r = idx >> 6, kc = idx & 63;
            float4 v = ldcg4((const float4*)(hsrc + (r0 + r) * HH) + kc);
            *(float4*)&h4s[(kc * 32 + r) * 4] = v;
        }
        if (tid < 32) {
            const float* xp = x + (((r0 + tid) * TT) + t) * 2;
            float amp = __ldg(xp), ph = __ldg(xp + 1);
            s_amp[tid] = amp;
            float sv, cv; sincosf(ph, &sv, &cv);
            s_sin[tid] = sv; s_cos[tid] = cv;
        }
        __syncthreads();

        // ---- GEMM1: 20 warps = 10 col-groups (4 cols) x 2 k-halves ----
        {
            int cg = wid % 10, kh = wid / 10;
            float a0 = 0.f, a1 = 0.f, a2 = 0.f, a3 = 0.f;
            const float* wp = W1s + cg * 4;
            #pragma unroll 4
            for (int kc = kh * 32; kc < kh * 32 + 32; ++kc) {
                float4 hv = *(const float4*)&h4s[(kc * 32 + lane) * 4];
                float4 w;
                w = *(const float4*)&wp[(kc * 4 + 0) * 40];
                a0 += hv.x * w.x; a1 += hv.x * w.y; a2 += hv.x * w.z; a3 += hv.x * w.w;
                w = *(const float4*)&wp[(kc * 4 + 1) * 40];
                a0 += hv.y * w.x; a1 += hv.y * w.y; a2 += hv.y * w.z; a3 += hv.y * w.w;
                w = *(const float4*)&wp[(kc * 4 + 2) * 40];
                a0 += hv.z * w.x; a1 += hv.z * w.y; a2 += hv.z * w.z; a3 += hv.z * w.w;
                w = *(const float4*)&wp[(kc * 4 + 3) * 40];
                a0 += hv.w * w.x; a1 += hv.w * w.y; a2 += hv.w * w.z; a3 += hv.w * w.w;
            }
            float* s = S1 + kh * 40 * 33;
            s[(cg * 4 + 0) * 33 + lane] = a0;
            s[(cg * 4 + 1) * 33 + lane] = a1;
            s[(cg * 4 + 2) * 33 + lane] = a2;
            s[(cg * 4 + 3) * 33 + lane] = a3;
        }
        __syncthreads();

        // ---- epilogue 1: a, p1, p2 -> u ----
        if (tid < 256) {
            int jj = tid & 7, r = tid >> 3;
            float a  = fast_tanh(S1[(0  + jj) * 33 + r] + S1[(40 * 33) + (0  + jj) * 33 + r]
                                 + s_amp[r] * s_w0[jj]      + s_b1[jj]);
            float p1 = fast_tanh(S1[(8  + jj) * 33 + r] + S1[(40 * 33) + (8  + jj) * 33 + r]
                                 + s_cos[r] * s_w0[8 + jj]  + s_b1[8 + jj]);
            float p2 = fast_tanh(S1[(16 + jj) * 33 + r] + S1[(40 * 33) + (16 + jj) * 33 + r]
                                 + s_sin[r] * s_w0[16 + jj] + s_b1[16 + jj]);
            g_u[(r0 + r) * HH + j0 + jj] =
                a * p1 * p2 * (1.f - a) * (1.f - p1) * (1.f - p2);
        }
        group_bar(fl, nj, base, ++ep);

        // ---- stage 2: load u tile ----
        for (int idx = tid; idx < 32 * 64; idx += NT) {
            int r = idx >> 6, kc = idx & 63;
            float4 v = ldcg4((const float4*)(g_u + (r0 + r) * HH) + kc);
            *(float4*)&u4s[(kc * 32 + r) * 4] = v;
        }
        __syncthreads();

        // ---- GEMM2: warps 0-15 = 4 col-groups (4 cols) x 4 k-quarters ----
        if (wid < 16) {
            int ng = wid & 3, kq = wid >> 2;
            float a0 = 0.f, a1 = 0.f, a2 = 0.f, a3 = 0.f;
            const float* wp = W2s + ng * 4;
            #pragma unroll 4
            for (int kc = kq * 16; kc < kq * 16 + 16; ++kc) {
                float4 uv = *(const float4*)&u4s[(kc * 32 + lane) * 4];
                float4 w;
                w = *(const float4*)&wp[(kc * 4 + 0) * 16];
                a0 += uv.x * w.x; a1 += uv.x * w.y; a2 += uv.x * w.z; a3 += uv.x * w.w;
                w = *(const float4*)&wp[(kc * 4 + 1) * 16];
                a0 += uv.y * w.x; a1 += uv.y * w.y; a2 += uv.y * w.z; a3 += uv.y * w.w;
                w = *(const float4*)&wp[(kc * 4 + 2) * 16];
                a0 += uv.z * w.x; a1 += uv.z * w.y; a2 += uv.z * w.z; a3 += uv.z * w.w;
                w = *(const float4*)&wp[(kc * 4 + 3) * 16];
                a0 += uv.w * w.x; a1 += uv.w * w.y; a2 += uv.w * w.z; a3 += uv.w * w.w;
            }
            float* s = S2 + kq * 16 * 33;
            s[(ng * 4 + 0) * 33 + lane] = a0;
            s[(ng * 4 + 1) * 33 + lane] = a1;
            s[(ng * 4 + 2) * 33 + lane] = a2;
            s[(ng * 4 + 3) * 33 + lane] = a3;
        } else if (nj == 0 && t >= 1) {
            // warps 16-19: output projection for step t-1 from h4s
            #pragma unroll
            for (int it = 0; it < 2; ++it) {
                int item = it * 128 + (wid - 16) * 32 + lane;
                int r = item >> 3, kk = item & 7;
                float o0 = 0.f, o1 = 0.f;
                for (int k = kk * 32; k < kk * 32 + 32; ++k) {
                    float v = h4s[(k >> 2) * 128 + r * 4 + (k & 3)];
                    o0 += v * s_Wo[k * 2];
                    o1 += v * s_Wo[k * 2 + 1];
                }
                o0 += __shfl_xor_sync(0xffffffffu, o0, 1);
                o0 += __shfl_xor_sync(0xffffffffu, o0, 2);
                o0 += __shfl_xor_sync(0xffffffffu, o0, 4);
                o1 += __shfl_xor_sync(0xffffffffu, o1, 1);
                o1 += __shfl_xor_sync(0xffffffffu, o1, 2);
                o1 += __shfl_xor_sync(0xffffffffu, o1, 4);
                if (kk == 0) {
                    float* op = out + (((r0 + r) * TT) + (t - 1)) * 2;
                    op[0] = o0 + s_bo[0];
                    op[1] = o1 + s_bo[1];
                }
            }
        }
        __syncthreads();

        // ---- epilogue 2: z, h_cand, h_new ----
        if (tid < 256) {
            int jj = tid & 7, r = tid >> 3;
            int j = j0 + jj;
            float zp = S2[(0 * 16 + jj) * 33 + r] + S2[(1 * 16 + jj) * 33 + r]
                     + S2[(2 * 16 + jj) * 33 + r] + S2[(3 * 16 + jj) * 33 + r]
                     + S1[(24 + jj) * 33 + r] + S1[(40 * 33) + (24 + jj) * 33 + r]
                     + s_bz[jj];
            float hp = S2[(0 * 16 + 8 + jj) * 33 + r] + S2[(1 * 16 + 8 + jj) * 33 + r]
                     + S2[(2 * 16 + 8 + jj) * 33 + r] + S2[(3 * 16 + 8 + jj) * 33 + r]
                     + S1[(32 + jj) * 33 + r] + S1[(40 * 33) + (32 + jj) * 33 + r]
                     + s_bh[jj];
            float z  = fast_sigmoid(zp);
            float hc = fast_tanh(hp);
            float hold = h4s[(j >> 2) * 128 + r * 4 + (j & 3)];
            float hn = z * hold + (1.f - z) * hc;
            g_h[(r0 + r) * HH + j] = hn;
            if (t == TT - 1)
                out[BB * TT * 2 + (r0 + r) * HH + j] = hn;
        }
        group_bar(fl, nj, base, ++ep);
    }

    // ---- final output row t=1023 from g_h ----
    if (nj == 0 && tid < 256) {
        int r = tid >> 3, kk = tid & 7;
        float o0 = 0.f, o1 = 0.f;
        for (int k = kk * 32; k < kk * 32 + 32; ++k) {
            float v = ldcg1(&g_h[(r0 + r) * HH + k]);
            o0 += v * s_Wo[k * 2];
            o1 += v * s_Wo[k * 2 + 1];
        }
        o0 += __shfl_xor_sync(0xffffffffu, o0, 1);
        o0 += __shfl_xor_sync(0xffffffffu, o0, 2);
        o0 += __shfl_xor_sync(0xffffffffu, o0, 4);
        o1 += __shfl_xor_sync(0xffffffffu, o1, 1);
        o1 += __shfl_xor_sync(0xffffffffu, o1, 2);
        o1 += __shfl_xor_sync(0xffffffffu, o1, 4);
        if (kk == 0) {
            float* op = out + (((r0 + r) * TT) + (TT - 1)) * 2;
            op[0] = o0 + s_bo[0];
            op[1] = o1 + s_bo[1];
        }
    }
}

extern "C" void kernel_launch(void* const* d_in, const int* in_sizes, int n_in,
                              void* d_out, int out_size) {
    const float* x   = (const float*)d_in[0];
    const float* h0  = (const float*)d_in[1];
    const float* Wa  = (const float*)d_in[2];
    const float* ba  = (const float*)d_in[3];
    const float* Wp1 = (const float*)d_in[4];
    const float* bp1 = (const float*)d_in[5];
    const float* Wp2 = (const float*)d_in[6];
    const float* bp2 = (const float*)d_in[7];
    const float* Wz  = (const float*)d_in[8];
    const float* bz  = (const float*)d_in[9];
    const float* Wh  = (const float*)d_in[10];
    const float* bh  = (const float*)d_in[11];
    const float* Wo  = (const float*)d_in[12];
    const float* bo  = (const float*)d_in[13];
    float* out = (float*)d_out;

    cudaFuncSetAttribute(pgjanet_kernel,
                         cudaFuncAttributeMaxDynamicSharedMemorySize, SMEM_BYTES);
    pgjanet_kernel<<<NCTA, NT, SMEM_BYTES>>>(
        x, h0, Wa, ba, Wp1, bp1, Wp2, bp2, Wz, bz, Wh, bh, Wo, bo, out);
}